// round 5
// baseline (speedup 1.0000x reference)
#include <cuda_runtime.h>
#include <cuda_bf16.h>

namespace {

constexpr int Bn  = 512;
constexpr int DKn = 256;
constexpr int DVn = 256;
constexpr int Pn  = 2048;
constexpr float SCALEf = 1.0f / 16.0f;   // 1/sqrt(256)

constexpr int K1_SPLIT = 4;              // P-chunks of 512 per energy CTA
constexpr int K1_P     = Pn / K1_SPLIT;  // 512
constexpr int K3_SPLIT = 8;              // DV-chunks of 32 rows per PV CTA
constexpr int K3_ROWS  = DVn / K3_SPLIT; // 32

} // namespace

// scratch: raw masked/scaled energies, then normalized softmax weights (in-place)
__device__ float g_W[(size_t)Bn * Pn];

namespace {

// ---------------- K1: e[b,p] = mask ? SCALE * sum_d Q[b,d]*K[b,d,p] : 0 ----------------
__global__ void __launch_bounds__(128)
energy_kernel(const float* __restrict__ Q,
              const float* __restrict__ K,
              const int*   __restrict__ mask)
{
    __shared__ float sQ[DKn];
    const int id = blockIdx.x;
    const int b  = id / K1_SPLIT;
    const int c  = id % K1_SPLIT;
    const int t  = threadIdx.x;

    sQ[t]       = Q[(size_t)b * DKn + t];
    sQ[t + 128] = Q[(size_t)b * DKn + t + 128];
    __syncthreads();

    const int p = c * K1_P + t * 4;
    const float* __restrict__ Kb = K + (size_t)b * DKn * Pn + p;

    float4 acc = make_float4(0.f, 0.f, 0.f, 0.f);

    #pragma unroll 1
    for (int d0 = 0; d0 < DKn; d0 += 16) {
        float4 kv[16];
        #pragma unroll
        for (int i = 0; i < 16; ++i)
            kv[i] = *reinterpret_cast<const float4*>(Kb + (size_t)(d0 + i) * Pn);
        #pragma unroll
        for (int i = 0; i < 16; ++i) {
            const float q = sQ[d0 + i];
            acc.x = fmaf(q, kv[i].x, acc.x);
            acc.y = fmaf(q, kv[i].y, acc.y);
            acc.z = fmaf(q, kv[i].z, acc.z);
            acc.w = fmaf(q, kv[i].w, acc.w);
        }
    }

    const int4 m = *reinterpret_cast<const int4*>(mask + (size_t)b * Pn + p);
    float4 e;
    e.x = m.x ? acc.x * SCALEf : 0.f;
    e.y = m.y ? acc.y * SCALEf : 0.f;
    e.z = m.z ? acc.z * SCALEf : 0.f;
    e.w = m.w ? acc.w * SCALEf : 0.f;
    *reinterpret_cast<float4*>(&g_W[(size_t)b * Pn + p]) = e;
}

// ---------------- K2: in-place normalized softmax over each row of g_W ----------------
__global__ void __launch_bounds__(256)
softmax_kernel()
{
    __shared__ float sRed[8];
    const int b    = blockIdx.x;
    const int t    = threadIdx.x;
    const int lane = t & 31;
    const int warp = t >> 5;

    float* __restrict__ W = g_W + (size_t)b * Pn;
    const int pA = 4 * t;
    const int pB = (Pn / 2) + 4 * t;

    const float4 eA = *reinterpret_cast<const float4*>(W + pA);
    const float4 eB = *reinterpret_cast<const float4*>(W + pB);
    float e[8] = {eA.x, eA.y, eA.z, eA.w, eB.x, eB.y, eB.z, eB.w};

    float lmax = e[0];
    #pragma unroll
    for (int i = 1; i < 8; ++i) lmax = fmaxf(lmax, e[i]);
    float v = lmax;
    #pragma unroll
    for (int o = 16; o; o >>= 1) v = fmaxf(v, __shfl_xor_sync(0xffffffffu, v, o));
    if (lane == 0) sRed[warp] = v;
    __syncthreads();
    float gmax = sRed[0];
    #pragma unroll
    for (int i = 1; i < 8; ++i) gmax = fmaxf(gmax, sRed[i]);
    __syncthreads();

    float w[8];
    float lsum = 0.f;
    #pragma unroll
    for (int i = 0; i < 8; ++i) {
        w[i] = __expf(e[i] - gmax);
        lsum += w[i];
    }
    v = lsum;
    #pragma unroll
    for (int o = 16; o; o >>= 1) v += __shfl_xor_sync(0xffffffffu, v, o);
    if (lane == 0) sRed[warp] = v;
    __syncthreads();
    float gsum = sRed[0];
    #pragma unroll
    for (int i = 1; i < 8; ++i) gsum += sRed[i];
    const float inv = 1.0f / gsum;

    *reinterpret_cast<float4*>(W + pA) =
        make_float4(w[0] * inv, w[1] * inv, w[2] * inv, w[3] * inv);
    *reinterpret_cast<float4*>(W + pB) =
        make_float4(w[4] * inv, w[5] * inv, w[6] * inv, w[7] * inv);
}

// ---------------- K3: out[b,vr] = sum_p w[b,p] * V[b,vr,p] ----------------
__global__ void __launch_bounds__(128)
pv_kernel(const float* __restrict__ V,
          float*       __restrict__ out)
{
    __shared__ float sW[Pn];
    const int id   = blockIdx.x;
    const int b    = id / K3_SPLIT;
    const int c    = id % K3_SPLIT;
    const int t    = threadIdx.x;
    const int lane = t & 31;
    const int warp = t >> 5;

    // stage normalized weights in smem (8 KB)
    #pragma unroll
    for (int i = 0; i < 4; ++i)
        *reinterpret_cast<float4*>(&sW[i * 512 + t * 4]) =
            *reinterpret_cast<const float4*>(&g_W[(size_t)b * Pn + i * 512 + t * 4]);
    __syncthreads();

    const float* __restrict__ Vb = V + (size_t)b * DVn * Pn;
    const int vr0 = c * K3_ROWS + warp * (K3_ROWS / 4);   // 8 rows per warp

    float s[K3_ROWS / 4];

    #pragma unroll 1
    for (int r = 0; r < K3_ROWS / 4; ++r) {
        const float* __restrict__ Vr = Vb + (size_t)(vr0 + r) * Pn + lane * 4;
        float4 acc = make_float4(0.f, 0.f, 0.f, 0.f);
        #pragma unroll
        for (int i = 0; i < Pn / 128; ++i) {       // 16 float4 loads in flight
            const float4 vv = *reinterpret_cast<const float4*>(Vr + i * 128);
            const float4 ww = *reinterpret_cast<const float4*>(&sW[i * 128 + lane * 4]);
            acc.x = fmaf(ww.x, vv.x, acc.x);
            acc.y = fmaf(ww.y, vv.y, acc.y);
            acc.z = fmaf(ww.z, vv.z, acc.z);
            acc.w = fmaf(ww.w, vv.w, acc.w);
        }
        s[r] = (acc.x + acc.y) + (acc.z + acc.w);  // no shfl inside the stream loop
    }

    // deferred cross-lane reduces
    #pragma unroll
    for (int r = 0; r < K3_ROWS / 4; ++r) {
        float v = s[r];
        #pragma unroll
        for (int o = 16; o; o >>= 1) v += __shfl_xor_sync(0xffffffffu, v, o);
        if (lane == 0) out[(size_t)b * DVn + vr0 + r] = v;
    }
}

} // namespace

extern "C" void kernel_launch(void* const* d_in, const int* in_sizes, int n_in,
                              void* d_out, int out_size)
{
    const float* Q    = (const float*)d_in[0];
    const float* K    = (const float*)d_in[1];
    const float* V    = (const float*)d_in[2];
    const int*   mask = (const int*)d_in[3];
    float*       out  = (float*)d_out;

    energy_kernel<<<Bn * K1_SPLIT, 128>>>(Q, K, mask);
    softmax_kernel<<<Bn, 256>>>();
    pv_kernel<<<Bn * K3_SPLIT, 128>>>(V, out);
}